// round 10
// baseline (speedup 1.0000x reference)
#include <cuda_runtime.h>
#include <cuda_fp16.h>
#include <cstdint>

#define BB 4
#define NN 4096
#define CC 64
#define CEXT 72            // 64 channels + ones col (64) + 7 zero pad
#define TI 128             // i rows per block
#define TJ 64              // j per stage
#define NST (NN / TJ)      // 64 stages
#define NBUF 3
#define NTHR 640           // 12 consumer warps + 8 producer warps

// half-precision smem geometry: 72 halves (144 B) row stride
#define ROWB 144
#define W_BYTES (128 * ROWB)              // 18432
#define O_BYTES (CEXT * ROWB)             // 10368
#define STG_B (W_BYTES + O_BYTES)         // 28800 per stage
#define SM_W2B  (NBUF * STG_B)            // 86400
#define SM_ZSHB (SM_W2B + 16384)
#define SMEM_BYTES (SM_ZSHB + 512)        // ~103 KB

__device__ __half g_outT[BB * CEXT * NN];  // [b][c][n] half; row 64 = ones
__device__ float  g_sl[BB * NN];
__device__ float  g_sr[BB * NN];

__device__ __forceinline__ float ex2f(float x) {
    float r;
    asm("ex2.approx.f32 %0, %1;" : "=f"(r) : "f"(x));
    return r;
}
__device__ __forceinline__ uint32_t smem_u32(const void* p) {
    uint32_t a;
    asm("{ .reg .u64 t; cvta.to.shared.u64 t, %1; cvt.u32.u64 %0, t; }" : "=r"(a) : "l"(p));
    return a;
}
__device__ __forceinline__ void mma_f16(float d[4], const uint32_t a[4],
                                        uint32_t b0, uint32_t b1) {
    asm volatile(
        "mma.sync.aligned.m16n8k16.row.col.f32.f16.f16.f32 "
        "{%0,%1,%2,%3},{%4,%5,%6,%7},{%8,%9},{%0,%1,%2,%3};"
        : "+f"(d[0]), "+f"(d[1]), "+f"(d[2]), "+f"(d[3])
        : "r"(a[0]), "r"(a[1]), "r"(a[2]), "r"(a[3]), "r"(b0), "r"(b1));
}
#define LDSM4(r, a) \
    asm volatile("ldmatrix.sync.aligned.m8n8.x4.shared.b16 {%0,%1,%2,%3}, [%4];" \
        : "=r"((r)[0]), "=r"((r)[1]), "=r"((r)[2]), "=r"((r)[3]) : "r"(a))
#define LDSM2(r, a) \
    asm volatile("ldmatrix.sync.aligned.m8n8.x2.shared.b16 {%0,%1}, [%2];" \
        : "=r"((r)[0]), "=r"((r)[1]) : "r"(a))
#define BAR_SYNC(id)   asm volatile("bar.sync %0, 640;"   :: "r"(id) : "memory")
#define BAR_ARRIVE(id) asm volatile("bar.arrive %0, 640;" :: "r"(id) : "memory")
#define CP_ASYNC16(dst, src) \
    asm volatile("cp.async.cg.shared.global [%0], [%1], 16;" :: "r"(dst), "l"(src) : "memory")
#define CP_COMMIT() asm volatile("cp.async.commit_group;" ::: "memory")
#define CP_WAIT0()  asm volatile("cp.async.wait_group 0;" ::: "memory")

// ---------------------------------------------------------------------------
// prep (unchanged, proven): out = X@W1; g_outT half transposed (+ones/zeros)
// ---------------------------------------------------------------------------
#define PREP_SMEM_FLOATS (4096 + 128 * 65 + 128)
__global__ __launch_bounds__(256) void prep_kernel(
    const float* __restrict__ X, const float* __restrict__ W1,
    const float* __restrict__ alpha)
{
    extern __shared__ float psm[];
    float* W1s = psm;
    float* Xs  = psm + 4096;
    float* al  = psm + 4096 + 128 * 65;
    float* ar  = al + 64;

    const int tid = threadIdx.x;
    const int gr0 = blockIdx.x * 128;
    const int b0  = gr0 >> 12;
    const int n0  = gr0 & (NN - 1);

    for (int i = tid; i < 1024; i += 256)
        reinterpret_cast<float4*>(W1s)[i] = reinterpret_cast<const float4*>(W1)[i];
    for (int i = tid; i < 2048; i += 256) {
        int r = i >> 4, q = i & 15;
        float4 v = reinterpret_cast<const float4*>(X + (size_t)(gr0 + r) * CC)[q];
        Xs[r * 65 + 4 * q + 0] = v.x; Xs[r * 65 + 4 * q + 1] = v.y;
        Xs[r * 65 + 4 * q + 2] = v.z; Xs[r * 65 + 4 * q + 3] = v.w;
    }
    if (tid < 64)       al[tid]      = alpha[tid];
    else if (tid < 128) ar[tid - 64] = alpha[tid];
    __syncthreads();

    const int r  = tid >> 2;
    const int c0 = tid & 3;

    float acc0[16], acc1[16];
#pragma unroll
    for (int q = 0; q < 16; q++) { acc0[q] = 0.f; acc1[q] = 0.f; }
    const float4* W1v = reinterpret_cast<const float4*>(W1s);
#pragma unroll 4
    for (int k = 0; k < 64; k++) {
        float x0 = Xs[r * 65 + k];
        float x1 = Xs[(r + 64) * 65 + k];
#pragma unroll
        for (int h = 0; h < 4; h++) {
            float4 wv = W1v[k * 16 + 4 * c0 + h];
            acc0[4 * h + 0] += x0 * wv.x; acc1[4 * h + 0] += x1 * wv.x;
            acc0[4 * h + 1] += x0 * wv.y; acc1[4 * h + 1] += x1 * wv.y;
            acc0[4 * h + 2] += x0 * wv.z; acc1[4 * h + 2] += x1 * wv.z;
            acc0[4 * h + 3] += x0 * wv.w; acc1[4 * h + 3] += x1 * wv.w;
        }
    }

    float vl0 = 0.f, vr0 = 0.f, vl1 = 0.f, vr1 = 0.f;
#pragma unroll
    for (int q = 0; q < 16; q++) {
        float a_ = al[16 * c0 + q], r_ = ar[16 * c0 + q];
        vl0 += acc0[q] * a_; vr0 += acc0[q] * r_;
        vl1 += acc1[q] * a_; vr1 += acc1[q] * r_;
    }
#pragma unroll
    for (int o = 1; o <= 2; o <<= 1) {
        vl0 += __shfl_xor_sync(0xffffffffu, vl0, o);
        vr0 += __shfl_xor_sync(0xffffffffu, vr0, o);
        vl1 += __shfl_xor_sync(0xffffffffu, vl1, o);
        vr1 += __shfl_xor_sync(0xffffffffu, vr1, o);
    }
    if (c0 == 0) {
        g_sl[gr0 + r] = vl0;       g_sr[gr0 + r] = vr0;
        g_sl[gr0 + r + 64] = vl1;  g_sr[gr0 + r + 64] = vr1;
    }

    __half* oT = g_outT;
    size_t base0 = (size_t)b0 * CEXT * NN + (n0 + r);
#pragma unroll
    for (int q = 0; q < 16; q++) {
        size_t coff = (size_t)(16 * c0 + q) * NN;
        oT[base0 + coff]      = __float2half_rn(acc0[q]);
        oT[base0 + 64 + coff] = __float2half_rn(acc1[q]);
    }

#pragma unroll
    for (int p = 0; p < 4; p++) {
        int it = tid + 256 * p;
        int rr = 64 + (it >> 7);
        int nn = n0 + (it & 127);
        g_outT[(size_t)b0 * CEXT * NN + (size_t)rr * NN + nn] =
            __float2half_rn((rr == 64) ? 1.0f : 0.0f);
    }
}

// ---------------------------------------------------------------------------
// attn: fp16 mma + ldmatrix, 640 threads = 12 consumer + 8 producer warps.
// Consumers: 4 wm (32 rows) x 3 wn (24 cols), uniform NT=3, 24 MMA/warp/stage.
// Producers: identical to R8 (the 137us best).
// barrier ids: full = 1+buf (1..3), empty = 4+buf (4..6)
// ---------------------------------------------------------------------------
__device__ __forceinline__ void consume_tile3(
    uint32_t wA, uint32_t wB, uint32_t wB2, float acc[2][3][4])
{
#pragma unroll
    for (int ks = 0; ks < 4; ks++) {
        const uint32_t ko = (uint32_t)ks * 32;
        uint32_t a0[4], a1[4], bb[6];
        LDSM4(a0, wA + ko);
        LDSM4(a1, wA + 2304 + ko);         // +16 rows
        LDSM4(bb + 0, wB + ko);            // nt 0,1
        LDSM2(bb + 4, wB2 + ko);           // nt 2
#pragma unroll
        for (int nt = 0; nt < 3; nt++) {
            mma_f16(acc[0][nt], a0, bb[2 * nt], bb[2 * nt + 1]);
            mma_f16(acc[1][nt], a1, bb[2 * nt], bb[2 * nt + 1]);
        }
    }
}

__global__ void __launch_bounds__(NTHR, 1) attn_kernel(
    const float* __restrict__ A_, const float* __restrict__ W2,
    float* __restrict__ out)
{
    extern __shared__ char sm[];
    const uint32_t smb = smem_u32(sm);
    float* W2s = reinterpret_cast<float*>(sm + SM_W2B);
    float* Zsh = reinterpret_cast<float*>(sm + SM_ZSHB);

    const int b      = blockIdx.y;
    const int i_base = blockIdx.x * TI;
    const int tid    = threadIdx.x;

    for (int i = tid; i < 1024; i += NTHR)
        reinterpret_cast<float4*>(W2s)[i] = reinterpret_cast<const float4*>(W2)[i];
    __syncthreads();

    if (tid < 384) {
        // ---------------- consumers (12 warps) ----------------
        const int lane = tid & 31, wid = tid >> 5;
        const int wm = wid & 3, wn = wid >> 2;          // wn 0..2
        const int r = lane >> 2, cq = lane & 3;
        const int moff = wm * 32, noff = wn * 24;

        const uint32_t aoff = (uint32_t)((lane & 15) * ROWB + (lane >> 4) * 16);
        const uint32_t boff = (uint32_t)((((lane & 7) + ((lane >> 4) & 1) * 8)) * ROWB
                                         + ((lane >> 3) & 1) * 16);
        const uint32_t boff2 = (uint32_t)((lane & 7) * ROWB + ((lane >> 3) & 1) * 16);

        const uint32_t wA  = smb + (uint32_t)moff * ROWB + aoff;
        const uint32_t wB  = smb + W_BYTES + (uint32_t)noff * ROWB + boff;
        const uint32_t wB2 = smb + W_BYTES + (uint32_t)(noff + 16) * ROWB + boff2;

        float acc[2][3][4];
#pragma unroll
        for (int mt = 0; mt < 2; mt++)
#pragma unroll
            for (int nt = 0; nt < 3; nt++)
#pragma unroll
                for (int e = 0; e < 4; e++) acc[mt][nt][e] = 0.f;

        for (int s = 0; s < NST; s++) {
            const int buf = (s >= 63) ? (s - 63) : s % NBUF;   // simple mod-3
            BAR_SYNC(1 + s % NBUF);
            const uint32_t bo = (uint32_t)(s % NBUF) * STG_B;
            consume_tile3(wA + bo, wB + bo, wB2 + bo, acc);
            BAR_ARRIVE(4 + s % NBUF);
            (void)buf;
        }

        // Z = ones column (col 64): wn==2, nt==2, frag col 0 (cq==0)
        if (wn == 2 && cq == 0) {
#pragma unroll
            for (int mt = 0; mt < 2; mt++) {
                int rr = moff + mt * 16 + r;
                Zsh[rr]     = acc[mt][2][0];
                Zsh[rr + 8] = acc[mt][2][2];
            }
        }
        __syncthreads();   // (A)

        float* aggS = reinterpret_cast<float*>(sm);   // 128 x 68 fp32
        const int ntmax = (wn == 2) ? 2 : 3;
#pragma unroll
        for (int mt = 0; mt < 2; mt++) {
            int rr = moff + mt * 16 + r;
            float z0 = 1.0f / Zsh[rr];
            float z1 = 1.0f / Zsh[rr + 8];
#pragma unroll
            for (int nt = 0; nt < 3; nt++) {
                if (nt >= ntmax) break;
                int col = noff + nt * 8 + 2 * cq;
                aggS[rr * 68 + col]           = acc[mt][nt][0] * z0;
                aggS[rr * 68 + col + 1]       = acc[mt][nt][1] * z0;
                aggS[(rr + 8) * 68 + col]     = acc[mt][nt][2] * z1;
                aggS[(rr + 8) * 68 + col + 1] = acc[mt][nt][3] * z1;
            }
        }
    } else {
        // ---------------- producers (8 warps, 256 threads; R8-identical) ----
        const int ptid = tid - 384;
        const int jj8  = ptid & 7;          // j cols 8*jj8 .. +7
        const int rgrp = ptid >> 3;         // rows rgrp + 32k, k<4
        const int j0   = 8 * jj8;

        const float*  Abase = A_ + (size_t)(i_base + rgrp) * NN + j0;
        const __half* oTb   = g_outT + (size_t)b * CEXT * NN;
        const float*  srb   = g_sr + b * NN + j0;

        float cl[4];
        unsigned fl[4];
#pragma unroll
        for (int k = 0; k < 4; k++) {
            float s_ = g_sl[b * NN + i_base + rgrp + 32 * k];
            fl[k] = (s_ > 0.f);
            cl[k] = fabsf(s_) * 1.44269504f;
        }

        uint32_t odst[3];
        int      osrc[3];
#pragma unroll
        for (int p = 0; p < 3; p++) {
            int it = ptid + 256 * p;
            int rr = it >> 3, q = it & 7;
            odst[p] = (uint32_t)(rr * ROWB + 16 * q);
            osrc[p] = rr * NN + 8 * q;
        }
        const bool ov2 = (ptid < 64);

        float4 a4[4][2], sr4[2];
        auto preload = [&](int s) {
            const int jb = s * TJ;
#pragma unroll
            for (int k = 0; k < 4; k++) {
                a4[k][0] = *reinterpret_cast<const float4*>(Abase + (size_t)(32 * k) * NN + jb);
                a4[k][1] = *reinterpret_cast<const float4*>(Abase + (size_t)(32 * k) * NN + jb + 4);
            }
            sr4[0] = *reinterpret_cast<const float4*>(srb + jb);
            sr4[1] = *reinterpret_cast<const float4*>(srb + jb + 4);
        };

        preload(0);
        for (int s = 0; s < NST; s++) {
            const int buf = s % NBUF;
            if (s >= NBUF) BAR_SYNC(4 + buf);
            const uint32_t bo = (uint32_t)buf * STG_B;
            const int jb = s * TJ;

            const uint32_t obase = smb + bo + W_BYTES;
#pragma unroll
            for (int p = 0; p < 2; p++)
                CP_ASYNC16(obase + odst[p], oTb + osrc[p] + jb);
            if (ov2) CP_ASYNC16(obase + odst[2], oTb + osrc[2] + jb);
            CP_COMMIT();

            if ((unsigned)(jb - i_base) < (unsigned)TI) {
                const int db = jb - i_base;
#pragma unroll
                for (int k = 0; k < 4; k++) {
                    int d = rgrp + 32 * k - db;
                    if ((unsigned)d < 64u && (d >> 3) == jj8)
                        reinterpret_cast<float*>(&a4[k][0])[d & 7] = 1.0f;
                }
            }

            float lp[8], lm[8];
            const float* srv = reinterpret_cast<const float*>(&sr4[0]);
#pragma unroll
            for (int e = 0; e < 8; e++) {
                lp[e] = fmaxf(srv[e], 0.01f * srv[e]);
                lm[e] = fmaxf(-srv[e], -0.01f * srv[e]);
            }

            uint4* wu = reinterpret_cast<uint4*>(sm + bo);
#pragma unroll
            for (int k = 0; k < 4; k++) {
                const float* av = reinterpret_cast<const float*>(&a4[k][0]);
                const int row = rgrp + 32 * k;
                uint32_t h[4];
#pragma unroll
                for (int e2 = 0; e2 < 4; e2++) {
                    float t0 = cl[k] * (fl[k] ? lp[2 * e2]     : lm[2 * e2]);
                    float t1 = cl[k] * (fl[k] ? lp[2 * e2 + 1] : lm[2 * e2 + 1]);
                    __half2 hv = __floats2half2_rn(ex2f(t0) * av[2 * e2],
                                                   ex2f(t1) * av[2 * e2 + 1]);
                    h[e2] = *reinterpret_cast<uint32_t*>(&hv);
                }
                wu[row * 9 + jj8] = make_uint4(h[0], h[1], h[2], h[3]);
            }

            CP_WAIT0();
            BAR_ARRIVE(1 + buf);
            if (s + 1 < NST) preload(s + 1);
        }
        __syncthreads();   // (A)
    }

    __syncthreads();       // (B) aggS ready

    // epilogue: out = aggS(128x64) @ W2(64x64), threads 0..511
    if (tid < 512) {
        const float* aggS = reinterpret_cast<const float*>(sm);
        const int r0 = tid >> 2;
        const int c0 = tid & 3;
        float res[16];
#pragma unroll
        for (int q = 0; q < 16; q++) res[q] = 0.f;
#pragma unroll 8
        for (int k = 0; k < 64; k++) {
            float a0 = aggS[r0 * 68 + k];
#pragma unroll
            for (int q = 0; q < 16; q++)
                res[q] += a0 * W2s[k * 64 + c0 + 4 * q];
        }
        float* ob = out + (size_t)(b * NN + i_base + r0) * CC;
#pragma unroll
        for (int q = 0; q < 16; q++)
            ob[c0 + 4 * q] = res[q];
    }
}

// ---------------------------------------------------------------------------
extern "C" void kernel_launch(void* const* d_in, const int* in_sizes, int n_in,
                              void* d_out, int out_size)
{
    (void)in_sizes; (void)n_in; (void)out_size;
    const float* X  = (const float*)d_in[0];
    const float* A_ = (const float*)d_in[1];
    const float* W1 = (const float*)d_in[2];
    const float* W2 = (const float*)d_in[3];
    const float* al = (const float*)d_in[4];
    float* out = (float*)d_out;

    cudaFuncSetAttribute(attn_kernel, cudaFuncAttributeMaxDynamicSharedMemorySize,
                         SMEM_BYTES);
    cudaFuncSetAttribute(prep_kernel, cudaFuncAttributeMaxDynamicSharedMemorySize,
                         PREP_SMEM_FLOATS * 4);

    prep_kernel<<<BB * NN / 128, 256, PREP_SMEM_FLOATS * 4>>>(X, W1, al);

    dim3 grid(NN / TI, BB);
    attn_kernel<<<grid, NTHR, SMEM_BYTES>>>(A_, W2, out);
}

// round 11
// speedup vs baseline: 1.0733x; 1.0733x over previous
#include <cuda_runtime.h>
#include <cuda_fp16.h>
#include <cstdint>

#define BB 4
#define NN 4096
#define CC 64
#define CEXT 72            // 64 channels + ones col (64) + 7 zero pad
#define TI 128             // i rows per block
#define TJ 128             // j per stage (2 producer halves)
#define NST (NN / TJ)      // 32 stages
#define NBUF 2
#define NTHR 512

// half-precision smem geometry: 136 halves (272 B) row stride
#define ROWB 272
#define W_BYTES (128 * ROWB)              // 34816
#define O_BYTES (CEXT * ROWB)             // 19584
#define STG_B (W_BYTES + O_BYTES)         // 54400 per stage
#define SM_W2B  (NBUF * STG_B)            // 108800
#define SM_ZSHB (SM_W2B + 16384)
#define SMEM_BYTES (SM_ZSHB + 512)        // ~126 KB

__device__ __half g_outT[BB * CEXT * NN];  // [b][c][n] half; row 64 = ones
__device__ float  g_sl[BB * NN];
__device__ float  g_sr[BB * NN];

__device__ __forceinline__ float ex2f(float x) {
    float r;
    asm("ex2.approx.f32 %0, %1;" : "=f"(r) : "f"(x));
    return r;
}
__device__ __forceinline__ uint32_t smem_u32(const void* p) {
    uint32_t a;
    asm("{ .reg .u64 t; cvta.to.shared.u64 t, %1; cvt.u32.u64 %0, t; }" : "=r"(a) : "l"(p));
    return a;
}
__device__ __forceinline__ void mma_f16(float d[4], const uint32_t a[4],
                                        uint32_t b0, uint32_t b1) {
    asm volatile(
        "mma.sync.aligned.m16n8k16.row.col.f32.f16.f16.f32 "
        "{%0,%1,%2,%3},{%4,%5,%6,%7},{%8,%9},{%0,%1,%2,%3};"
        : "+f"(d[0]), "+f"(d[1]), "+f"(d[2]), "+f"(d[3])
        : "r"(a[0]), "r"(a[1]), "r"(a[2]), "r"(a[3]), "r"(b0), "r"(b1));
}
#define LDSM4(r, a) \
    asm volatile("ldmatrix.sync.aligned.m8n8.x4.shared.b16 {%0,%1,%2,%3}, [%4];" \
        : "=r"((r)[0]), "=r"((r)[1]), "=r"((r)[2]), "=r"((r)[3]) : "r"(a))
#define LDSM2(r, a) \
    asm volatile("ldmatrix.sync.aligned.m8n8.x2.shared.b16 {%0,%1}, [%2];" \
        : "=r"((r)[0]), "=r"((r)[1]) : "r"(a))
#define BAR_SYNC(id)   asm volatile("bar.sync %0, 512;"   :: "r"(id) : "memory")
#define BAR_ARRIVE(id) asm volatile("bar.arrive %0, 512;" :: "r"(id) : "memory")
#define CP_ASYNC16(dst, src) \
    asm volatile("cp.async.cg.shared.global [%0], [%1], 16;" :: "r"(dst), "l"(src) : "memory")
#define CP_COMMIT() asm volatile("cp.async.commit_group;" ::: "memory")
#define CP_WAIT0()  asm volatile("cp.async.wait_group 0;" ::: "memory")

// ---------------------------------------------------------------------------
// prep (unchanged, proven): out = X@W1; g_outT half transposed (+ones/zeros)
// ---------------------------------------------------------------------------
#define PREP_SMEM_FLOATS (4096 + 128 * 65 + 128)
__global__ __launch_bounds__(256) void prep_kernel(
    const float* __restrict__ X, const float* __restrict__ W1,
    const float* __restrict__ alpha)
{
    extern __shared__ float psm[];
    float* W1s = psm;
    float* Xs  = psm + 4096;
    float* al  = psm + 4096 + 128 * 65;
    float* ar  = al + 64;

    const int tid = threadIdx.x;
    const int gr0 = blockIdx.x * 128;
    const int b0  = gr0 >> 12;
    const int n0  = gr0 & (NN - 1);

    for (int i = tid; i < 1024; i += 256)
        reinterpret_cast<float4*>(W1s)[i] = reinterpret_cast<const float4*>(W1)[i];
    for (int i = tid; i < 2048; i += 256) {
        int r = i >> 4, q = i & 15;
        float4 v = reinterpret_cast<const float4*>(X + (size_t)(gr0 + r) * CC)[q];
        Xs[r * 65 + 4 * q + 0] = v.x; Xs[r * 65 + 4 * q + 1] = v.y;
        Xs[r * 65 + 4 * q + 2] = v.z; Xs[r * 65 + 4 * q + 3] = v.w;
    }
    if (tid < 64)       al[tid]      = alpha[tid];
    else if (tid < 128) ar[tid - 64] = alpha[tid];
    __syncthreads();

    const int r  = tid >> 2;
    const int c0 = tid & 3;

    float acc0[16], acc1[16];
#pragma unroll
    for (int q = 0; q < 16; q++) { acc0[q] = 0.f; acc1[q] = 0.f; }
    const float4* W1v = reinterpret_cast<const float4*>(W1s);
#pragma unroll 4
    for (int k = 0; k < 64; k++) {
        float x0 = Xs[r * 65 + k];
        float x1 = Xs[(r + 64) * 65 + k];
#pragma unroll
        for (int h = 0; h < 4; h++) {
            float4 wv = W1v[k * 16 + 4 * c0 + h];
            acc0[4 * h + 0] += x0 * wv.x; acc1[4 * h + 0] += x1 * wv.x;
            acc0[4 * h + 1] += x0 * wv.y; acc1[4 * h + 1] += x1 * wv.y;
            acc0[4 * h + 2] += x0 * wv.z; acc1[4 * h + 2] += x1 * wv.z;
            acc0[4 * h + 3] += x0 * wv.w; acc1[4 * h + 3] += x1 * wv.w;
        }
    }

    float vl0 = 0.f, vr0 = 0.f, vl1 = 0.f, vr1 = 0.f;
#pragma unroll
    for (int q = 0; q < 16; q++) {
        float a_ = al[16 * c0 + q], r_ = ar[16 * c0 + q];
        vl0 += acc0[q] * a_; vr0 += acc0[q] * r_;
        vl1 += acc1[q] * a_; vr1 += acc1[q] * r_;
    }
#pragma unroll
    for (int o = 1; o <= 2; o <<= 1) {
        vl0 += __shfl_xor_sync(0xffffffffu, vl0, o);
        vr0 += __shfl_xor_sync(0xffffffffu, vr0, o);
        vl1 += __shfl_xor_sync(0xffffffffu, vl1, o);
        vr1 += __shfl_xor_sync(0xffffffffu, vr1, o);
    }
    if (c0 == 0) {
        g_sl[gr0 + r] = vl0;       g_sr[gr0 + r] = vr0;
        g_sl[gr0 + r + 64] = vl1;  g_sr[gr0 + r + 64] = vr1;
    }

    __half* oT = g_outT;
    size_t base0 = (size_t)b0 * CEXT * NN + (n0 + r);
#pragma unroll
    for (int q = 0; q < 16; q++) {
        size_t coff = (size_t)(16 * c0 + q) * NN;
        oT[base0 + coff]      = __float2half_rn(acc0[q]);
        oT[base0 + 64 + coff] = __float2half_rn(acc1[q]);
    }

#pragma unroll
    for (int p = 0; p < 4; p++) {
        int it = tid + 256 * p;
        int rr = 64 + (it >> 7);
        int nn = n0 + (it & 127);
        g_outT[(size_t)b0 * CEXT * NN + (size_t)rr * NN + nn] =
            __float2half_rn((rr == 64) ? 1.0f : 0.0f);
    }
}

// ---------------------------------------------------------------------------
// attn: fp16 mma + ldmatrix, TJ=128 (32 stages), producer does 2 j-halves
// per barrier period. 512 threads: warps 0..7 consumers, 8..15 producers.
// barrier ids: full = 1+buf (1..2), empty = 3+buf (3..4)
// ---------------------------------------------------------------------------
template<int NT>
__device__ __forceinline__ void consume_tile(
    uint32_t wA, uint32_t wB, uint32_t wB2, float acc[2][5][4])
{
#pragma unroll
    for (int ks = 0; ks < 8; ks++) {
        const uint32_t ko = (uint32_t)ks * 32;
        uint32_t a0[4], a1[4], bb[10];
        LDSM4(a0, wA + ko);
        LDSM4(a1, wA + 16 * ROWB + ko);    // +16 rows
        LDSM4(bb + 0, wB + ko);            // nt 0,1
        LDSM4(bb + 4, wB + 16 * ROWB + ko);// nt 2,3
        if (NT == 5) LDSM2(bb + 8, wB2 + ko);
#pragma unroll
        for (int nt = 0; nt < NT; nt++) {
            mma_f16(acc[0][nt], a0, bb[2 * nt], bb[2 * nt + 1]);
            mma_f16(acc[1][nt], a1, bb[2 * nt], bb[2 * nt + 1]);
        }
    }
}

__global__ void __launch_bounds__(NTHR, 1) attn_kernel(
    const float* __restrict__ A_, const float* __restrict__ W2,
    float* __restrict__ out)
{
    extern __shared__ char sm[];
    const uint32_t smb = smem_u32(sm);
    float* W2s = reinterpret_cast<float*>(sm + SM_W2B);
    float* Zsh = reinterpret_cast<float*>(sm + SM_ZSHB);

    const int b      = blockIdx.y;
    const int i_base = blockIdx.x * TI;
    const int tid    = threadIdx.x;

    for (int i = tid; i < 1024; i += NTHR)
        reinterpret_cast<float4*>(W2s)[i] = reinterpret_cast<const float4*>(W2)[i];
    __syncthreads();

    if (tid < 256) {
        // ---------------- consumers (8 warps) ----------------
        const int lane = tid & 31, wid = tid >> 5;
        const int wm = wid & 3, wn = wid >> 2;
        const int r = lane >> 2, cq = lane & 3;
        const int moff = wm * 32, noff = wn * 40;

        const uint32_t aoff = (uint32_t)((lane & 15) * ROWB + (lane >> 4) * 16);
        const uint32_t boff = (uint32_t)((((lane & 7) + ((lane >> 4) & 1) * 8)) * ROWB
                                         + ((lane >> 3) & 1) * 16);
        const uint32_t boff2 = (uint32_t)((lane & 7) * ROWB + ((lane >> 3) & 1) * 16);

        const uint32_t wA  = smb + (uint32_t)moff * ROWB + aoff;
        const uint32_t wB  = smb + W_BYTES + (uint32_t)noff * ROWB + boff;
        const uint32_t wB2 = smb + W_BYTES + (uint32_t)(noff + 32) * ROWB + boff2;

        float acc[2][5][4];
#pragma unroll
        for (int mt = 0; mt < 2; mt++)
#pragma unroll
            for (int nt = 0; nt < 5; nt++)
#pragma unroll
                for (int e = 0; e < 4; e++) acc[mt][nt][e] = 0.f;

        for (int s = 0; s < NST; s++) {
            const int buf = s & 1;
            BAR_SYNC(1 + buf);
            const uint32_t bo = (uint32_t)buf * STG_B;
            if (wn == 0) consume_tile<5>(wA + bo, wB + bo, wB2 + bo, acc);
            else         consume_tile<4>(wA + bo, wB + bo, wB2 + bo, acc);
            BAR_ARRIVE(3 + buf);
        }

        // Z = ones column (col 64): wn==1, nt==3, frag col 0 (cq==0)
        if (wn == 1 && cq == 0) {
#pragma unroll
            for (int mt = 0; mt < 2; mt++) {
                int rr = moff + mt * 16 + r;
                Zsh[rr]     = acc[mt][3][0];
                Zsh[rr + 8] = acc[mt][3][2];
            }
        }
        __syncthreads();   // (A)

        float* aggS = reinterpret_cast<float*>(sm);   // 128 x 68 fp32 (stride 68)
        const int ntmax = (wn == 0) ? 5 : 3;
#pragma unroll
        for (int mt = 0; mt < 2; mt++) {
            int rr = moff + mt * 16 + r;
            float z0 = 1.0f / Zsh[rr];
            float z1 = 1.0f / Zsh[rr + 8];
#pragma unroll
            for (int nt = 0; nt < 5; nt++) {
                if (nt >= ntmax) break;
                int col = noff + nt * 8 + 2 * cq;
                aggS[rr * 68 + col]           = acc[mt][nt][0] * z0;
                aggS[rr * 68 + col + 1]       = acc[mt][nt][1] * z0;
                aggS[(rr + 8) * 68 + col]     = acc[mt][nt][2] * z1;
                aggS[(rr + 8) * 68 + col + 1] = acc[mt][nt][3] * z1;
            }
        }
    } else {
        // ---------------- producers (8 warps, 256 threads) ----------------
        const int ptid = tid - 256;
        const int jj8  = ptid & 7;          // 8-col group within a 64-wide half
        const int rgrp = ptid >> 3;         // rows rgrp + 32k, k<4

        const float*  Abase = A_ + (size_t)(i_base + rgrp) * NN + 8 * jj8;
        const __half* oTb   = g_outT + (size_t)b * CEXT * NN;
        const float*  srb   = g_sr + b * NN + 8 * jj8;

        float cl[4];
        unsigned fl[4];
#pragma unroll
        for (int k = 0; k < 4; k++) {
            float s_ = g_sl[b * NN + i_base + rgrp + 32 * k];
            fl[k] = (s_ > 0.f);
            cl[k] = fabsf(s_) * 1.44269504f;
        }

        // o-tile cp.async: 72 rows x 16 chunks (16B) = 1152
        uint32_t odst[5];
        int      osrc[5];
#pragma unroll
        for (int p = 0; p < 5; p++) {
            int it = ptid + 256 * p;
            int rr = it >> 4, q = it & 15;
            odst[p] = (uint32_t)(rr * ROWB + 16 * q);
            osrc[p] = rr * NN + 8 * q;
        }
        const bool ov4 = (ptid < 128);      // p=4 only for it < 1152

        float4 a4[4][2], sr4[2][2];

        auto load_half = [&](int jb, int h) {   // A cols jb + 64h + 8*jj8 .. +7
            const int off = jb + 64 * h;
#pragma unroll
            for (int k = 0; k < 4; k++) {
                a4[k][0] = *reinterpret_cast<const float4*>(Abase + (size_t)(32 * k) * NN + off);
                a4[k][1] = *reinterpret_cast<const float4*>(Abase + (size_t)(32 * k) * NN + off + 4);
            }
        };
        auto load_sr = [&](int jb) {
            sr4[0][0] = *reinterpret_cast<const float4*>(srb + jb);
            sr4[0][1] = *reinterpret_cast<const float4*>(srb + jb + 4);
            sr4[1][0] = *reinterpret_cast<const float4*>(srb + jb + 64);
            sr4[1][1] = *reinterpret_cast<const float4*>(srb + jb + 68);
        };

        auto compute_half = [&](int h, int jb, uint4* wu) {
            // diagonal fixup: rows k = 2h, 2h+1 have their diag col in half h
            if (jb == i_base) {
#pragma unroll
                for (int kk = 0; kk < 2; kk++) {
                    int k = 2 * h + kk;
                    int colh = rgrp + 32 * kk;   // col within half
                    if ((colh >> 3) == jj8)
                        reinterpret_cast<float*>(&a4[k][0])[colh & 7] = 1.0f;
                }
            }
            float lp[8], lm[8];
            const float* srv = reinterpret_cast<const float*>(&sr4[h][0]);
#pragma unroll
            for (int e = 0; e < 8; e++) {
                lp[e] = fmaxf(srv[e], 0.01f * srv[e]);
                lm[e] = fmaxf(-srv[e], -0.01f * srv[e]);
            }
#pragma unroll
            for (int k = 0; k < 4; k++) {
                const float* av = reinterpret_cast<const float*>(&a4[k][0]);
                const int row = rgrp + 32 * k;
                uint32_t hh[4];
#pragma unroll
                for (int e2 = 0; e2 < 4; e2++) {
                    float t0 = cl[k] * (fl[k] ? lp[2 * e2]     : lm[2 * e2]);
                    float t1 = cl[k] * (fl[k] ? lp[2 * e2 + 1] : lm[2 * e2 + 1]);
                    __half2 hv = __floats2half2_rn(ex2f(t0) * av[2 * e2],
                                                   ex2f(t1) * av[2 * e2 + 1]);
                    hh[e2] = *reinterpret_cast<uint32_t*>(&hv);
                }
                wu[row * (ROWB / 16) + 8 * h + jj8] =
                    make_uint4(hh[0], hh[1], hh[2], hh[3]);
            }
        };

        load_half(0, 0);
        load_sr(0);

        for (int s = 0; s < NST; s++) {
            const int buf = s & 1;
            if (s >= NBUF) BAR_SYNC(3 + buf);
            const uint32_t bo = (uint32_t)buf * STG_B;
            const int jb = s * TJ;

            // o-tile async copy (full 128 cols)
            const uint32_t obase = smb + bo + W_BYTES;
#pragma unroll
            for (int p = 0; p < 4; p++)
                CP_ASYNC16(obase + odst[p], oTb + osrc[p] + jb);
            if (ov4) CP_ASYNC16(obase + odst[4], oTb + osrc[4] + jb);
            CP_COMMIT();

            uint4* wu = reinterpret_cast<uint4*>(sm + bo);
            compute_half(0, jb, wu);       // a4 holds half 0 (preloaded)
            load_half(jb, 1);              // reload a4 with half 1 (exposed ~L2)
            compute_half(1, jb, wu);

            CP_WAIT0();
            BAR_ARRIVE(1 + buf);
            if (s + 1 < NST) {             // preload half 0 of next stage
                load_half((s + 1) * TJ, 0);
                load_sr((s + 1) * TJ);
            }
        }
        __syncthreads();   // (A)
    }

    __syncthreads();       // (B) aggS ready

    // epilogue: out = aggS(128x64) @ W2(64x64), all 512 threads
    const float* aggS = reinterpret_cast<const float*>(sm);
    const int r0 = tid >> 2;
    const int c0 = tid & 3;
    float res[16];
#pragma unroll
    for (int q = 0; q < 16; q++) res[q] = 0.f;
#pragma unroll 8
    for (int k = 0; k < 64; k++) {
        float a0 = aggS[r0 * 68 + k];
#pragma unroll
        for (int q = 0; q < 16; q++)
            res[q] += a0 * W2s[k * 64 + c0 + 4 * q];
    }
    float* ob = out + (size_t)(b * NN + i_base + r0) * CC;
#pragma unroll
    for (int q = 0; q < 16; q++)
        ob[c0 + 4 * q] = res[q];
}

// ---------------------------------------------------------------------------
extern "C" void kernel_launch(void* const* d_in, const int* in_sizes, int n_in,
                              void* d_out, int out_size)
{
    (void)in_sizes; (void)n_in; (void)out_size;
    const float* X  = (const float*)d_in[0];
    const float* A_ = (const float*)d_in[1];
    const float* W1 = (const float*)d_in[2];
    const float* W2 = (const float*)d_in[3];
    const float* al = (const float*)d_in[4];
    float* out = (float*)d_out;

    cudaFuncSetAttribute(attn_kernel, cudaFuncAttributeMaxDynamicSharedMemorySize,
                         SMEM_BYTES);
    cudaFuncSetAttribute(prep_kernel, cudaFuncAttributeMaxDynamicSharedMemorySize,
                         PREP_SMEM_FLOATS * 4);

    prep_kernel<<<BB * NN / 128, 256, PREP_SMEM_FLOATS * 4>>>(X, W1, al);

    dim3 grid(NN / TI, BB);
    attn_kernel<<<grid, NTHR, SMEM_BYTES>>>(A_, W2, out);
}